// round 4
// baseline (speedup 1.0000x reference)
#include <cuda_runtime.h>
#include <math.h>
#include <stdint.h>

#define T_TOK 8192
#define D_EMB 1024
#define HID   4096
#define ADP   256
#define NEXP  8
#define GRP   16

// ---------------- scratch (device globals, allocation-free) ----------------
__device__ __align__(16) float g_H[(size_t)T_TOK * HID];
__device__ __align__(16) float g_A[T_TOK * ADP];
__device__ __align__(16) float g_AN[T_TOK * ADP];
__device__ __align__(16) float g_WepT[ADP * HID];   // W_ep^T  [ADP, HID]
__device__ __align__(16) float g_Wc[D_EMB * ADP];   // 0.1 * W_out @ W_ep  [D, ADP]
__device__ int g_route[T_TOK];
__device__ int g_perm[T_TOK];
__device__ int g_cnt[NEXP];
__device__ int g_cur[NEXP];
__device__ int g_off[NEXP + 1];
__device__ int g_blkoff[NEXP + 1];

// ---------------------------------------------------------------------------
// Routing / grouping
// ---------------------------------------------------------------------------
__global__ void init_kernel() {
    if (threadIdx.x < NEXP) g_cnt[threadIdx.x] = 0;
}
__global__ void route_kernel(const float* __restrict__ ew) {
    int t = blockIdx.x * blockDim.x + threadIdx.x;
    if (t >= T_TOK) return;
    int last = -1;
#pragma unroll
    for (int e = 0; e < NEXP; e++)
        if (ew[t * NEXP + e] > 0.0f) last = e;
    g_route[t] = last;
    if (last >= 0) atomicAdd(&g_cnt[last], 1);
}
__global__ void scan_kernel() {
    if (threadIdx.x == 0) {
        int off = 0, boff = 0;
        g_off[0] = 0; g_blkoff[0] = 0;
        for (int e = 0; e < NEXP; e++) {
            g_cur[e] = 0;
            off += g_cnt[e];                     g_off[e + 1] = off;
            boff += (g_cnt[e] + GRP - 1) / GRP;  g_blkoff[e + 1] = boff;
        }
    }
}
__global__ void scatter_kernel() {
    int t = blockIdx.x * blockDim.x + threadIdx.x;
    if (t >= T_TOK) return;
    int e = g_route[t];
    if (e >= 0) g_perm[g_off[e] + atomicAdd(&g_cur[e], 1)] = t;
}

// ---------------------------------------------------------------------------
// W_ep transpose: [HID, ADP] -> [ADP, HID]
// ---------------------------------------------------------------------------
__global__ void transpose_kernel(const float* __restrict__ in, float* __restrict__ outp) {
    __shared__ float tile[32][33];
    int x = blockIdx.x * 32 + threadIdx.x;
    int y0 = blockIdx.y * 32;
#pragma unroll
    for (int j = 0; j < 32; j += 8)
        tile[threadIdx.y + j][threadIdx.x] = in[(size_t)x * ADP + y0 + threadIdx.y + j];
    __syncthreads();
    int xo = blockIdx.y * 32 + threadIdx.x;
    int yo = blockIdx.x * 32;
#pragma unroll
    for (int j = 0; j < 32; j += 8)
        outp[(size_t)xo * HID + yo + threadIdx.y + j] = tile[threadIdx.x][threadIdx.y + j];
}

// ---------------------------------------------------------------------------
// TF32 mma.sync NT GEMM, fragment-packed smem layout.
// C[M,N] = epi( [A0|A1] @ [B0|B1]^T ), K = K0 + K1 (K1=0 unless CONCAT).
//   MODE 0: silu(acc)   MODE 1: acc   MODE 2: 0.1*acc
// BM=BN=128, BK=16, 256 thr (8 warps 2x4), warp tile 64x32, double buffer.
// Smem layout is permuted so a-fragments load with one LDS.128 and
// b-fragments with one LDS.64 (vs 4/2 scalar LDS).
// ---------------------------------------------------------------------------
__device__ __forceinline__ unsigned f2tf32(float x) {
    unsigned u; asm("cvt.rna.tf32.f32 %0, %1;" : "=r"(u) : "f"(x)); return u;
}
__device__ __forceinline__ void mma8(float* d, const unsigned* a, const unsigned* b) {
    asm volatile(
        "mma.sync.aligned.m16n8k8.row.col.f32.tf32.tf32.f32 "
        "{%0,%1,%2,%3}, {%4,%5,%6,%7}, {%8,%9}, {%0,%1,%2,%3};\n"
        : "+f"(d[0]), "+f"(d[1]), "+f"(d[2]), "+f"(d[3])
        : "r"(a[0]), "r"(a[1]), "r"(a[2]), "r"(a[3]), "r"(b[0]), "r"(b[1]));
}

template <int MODE, bool CONCAT>
__global__ void __launch_bounds__(256, 2)
gemm_tf32(const float* __restrict__ A0, const float* __restrict__ B0, int K0,
          const float* __restrict__ A1, const float* __restrict__ B1, int K1,
          float* __restrict__ C, int M, int N) {
    // 2 stages x 2048 words each
    __shared__ __align__(16) unsigned As[2][2048];
    __shared__ __align__(16) unsigned Bs[2][2048];

    const int tid = threadIdx.x;
    const int lane = tid & 31, warp = tid >> 5;
    const int wm = warp >> 2, wn = warp & 3;
    const int g = lane >> 2, c = lane & 3;
    const int m0 = blockIdx.y * 128, n0 = blockIdx.x * 128;

    const int r = tid >> 1;      // row within tile (0..127)
    const int h = tid & 1;       // k-half (ks) of BK=16

    // store-side base indices (fragment-packed layout)
    // A: idx = ((((ks*2 + m>>6)*4 + (m>>4&3))*32) + (m&7)*4 + c)*4 + (m>>3&1) + 2*q
    const int baseA_idx =
        ((((h * 2 + (r >> 6)) * 4 + ((r >> 4) & 3)) * 32 + (r & 7) * 4) * 4) + ((r >> 3) & 1);
    // B: idx = ((((ks*4 + n>>5)*4 + (n>>3&3))*32) + (n&7)*4 + c)*2 + q
    const int baseB_idx =
        (((h * 4 + (r >> 5)) * 4 + ((r >> 3) & 3)) * 32 + (r & 7) * 4) * 2;

    float acc[4][4][4];
#pragma unroll
    for (int i = 0; i < 4; i++)
#pragma unroll
        for (int j = 0; j < 4; j++)
#pragma unroll
            for (int k = 0; k < 4; k++) acc[i][j][k] = 0.0f;

    const int KT = (K0 + K1) / 16;

    // gmem pointers for this thread's (row, k-half)
    auto ld_tile = [&](int kt, float4& ra0, float4& ra1, float4& rb0, float4& rb1) {
        int kg = kt * 16 + h * 8;
        const float* ap;
        const float* bp;
        if (!CONCAT || kg < K0) {
            ap = A0 + (size_t)(m0 + r) * K0 + kg;
            bp = B0 + (size_t)(n0 + r) * K0 + kg;
        } else {
            int kk = kg - K0;
            ap = A1 + (size_t)(m0 + r) * K1 + kk;
            bp = B1 + (size_t)(n0 + r) * K1 + kk;
        }
        ra0 = *(const float4*)(ap);
        ra1 = *(const float4*)(ap + 4);
        rb0 = *(const float4*)(bp);
        rb1 = *(const float4*)(bp + 4);
    };

    auto st_tile = [&](int buf, const float4& ra0, const float4& ra1,
                       const float4& rb0, const float4& rb1) {
        unsigned* pa = &As[buf][baseA_idx];
        unsigned* pb = &Bs[buf][baseB_idx];
        // A: q=0 -> word off 0, q=1 -> word off 2; j -> +4 words
        pa[0]      = f2tf32(ra0.x); pa[4]      = f2tf32(ra0.y);
        pa[8]      = f2tf32(ra0.z); pa[12]     = f2tf32(ra0.w);
        pa[2]      = f2tf32(ra1.x); pa[6]      = f2tf32(ra1.y);
        pa[10]     = f2tf32(ra1.z); pa[14]     = f2tf32(ra1.w);
        // B: q -> word off, j -> +2 words
        pb[0]      = f2tf32(rb0.x); pb[2]      = f2tf32(rb0.y);
        pb[4]      = f2tf32(rb0.z); pb[6]      = f2tf32(rb0.w);
        pb[1]      = f2tf32(rb1.x); pb[3]      = f2tf32(rb1.y);
        pb[5]      = f2tf32(rb1.z); pb[7]      = f2tf32(rb1.w);
    };

    // prologue: tile 0 -> buf 0
    {
        float4 a0, a1, b0, b1;
        ld_tile(0, a0, a1, b0, b1);
        st_tile(0, a0, a1, b0, b1);
    }
    __syncthreads();

    for (int kt = 0; kt < KT; kt++) {
        const int buf = kt & 1;
        float4 a0, a1, b0, b1;
        if (kt + 1 < KT) ld_tile(kt + 1, a0, a1, b0, b1);

#pragma unroll
        for (int ks = 0; ks < 2; ks++) {
            unsigned af[4][4];
            unsigned bf[4][2];
#pragma unroll
            for (int mi = 0; mi < 4; mi++) {
                const uint4 v = *(const uint4*)&As[buf][(((ks * 2 + wm) * 4 + mi) * 32 + lane) * 4];
                af[mi][0] = v.x; af[mi][1] = v.y; af[mi][2] = v.z; af[mi][3] = v.w;
            }
#pragma unroll
            for (int ni = 0; ni < 4; ni++) {
                const uint2 v = *(const uint2*)&Bs[buf][(((ks * 4 + wn) * 4 + ni) * 32 + lane) * 2];
                bf[ni][0] = v.x; bf[ni][1] = v.y;
            }
#pragma unroll
            for (int mi = 0; mi < 4; mi++)
#pragma unroll
                for (int ni = 0; ni < 4; ni++)
                    mma8(acc[mi][ni], af[mi], bf[ni]);
        }

        if (kt + 1 < KT) st_tile(buf ^ 1, a0, a1, b0, b1);
        __syncthreads();
    }

    // epilogue: direct register -> gmem
#pragma unroll
    for (int mi = 0; mi < 4; mi++) {
        int row0 = m0 + wm * 64 + mi * 16 + g;
#pragma unroll
        for (int ni = 0; ni < 4; ni++) {
            int col = n0 + wn * 32 + ni * 8 + 2 * c;
            float* p0 = C + (size_t)row0 * N + col;
            float* p1 = C + (size_t)(row0 + 8) * N + col;
            float v0 = acc[mi][ni][0], v1 = acc[mi][ni][1];
            float v2 = acc[mi][ni][2], v3 = acc[mi][ni][3];
            if (MODE == 0) {
                v0 = v0 / (1.0f + __expf(-v0)); v1 = v1 / (1.0f + __expf(-v1));
                v2 = v2 / (1.0f + __expf(-v2)); v3 = v3 / (1.0f + __expf(-v3));
            }
            if (MODE == 2) { v0 *= 0.1f; v1 *= 0.1f; v2 *= 0.1f; v3 *= 0.1f; }
            p0[0] = v0; p0[1] = v1;
            p1[0] = v2; p1[1] = v3;
        }
    }
}

// ---------------------------------------------------------------------------
// Grouped adapter matvec + fused LayerNorm
// ---------------------------------------------------------------------------
__global__ void __launch_bounds__(256)
adapter_grouped(const float* __restrict__ Wexp,
                const float* __restrict__ gamma,
                const float* __restrict__ beta) {
    __shared__ float a_sh[ADP][GRP];
    __shared__ float c_sh[GRP][ADP];
    __shared__ int s_tok[GRP];
    __shared__ int s_meta[3];

    const int b = blockIdx.x;
    if (threadIdx.x == 0) {
        int e = 0;
        while (e < NEXP && b >= g_blkoff[e + 1]) e++;
        if (e >= NEXP) s_meta[0] = -1;
        else {
            int base = g_off[e] + (b - g_blkoff[e]) * GRP;
            s_meta[0] = e; s_meta[1] = base;
            s_meta[2] = min(GRP, g_off[e + 1] - base);
        }
    }
    __syncthreads();
    const int e = s_meta[0];
    if (e < 0) return;
    const int base = s_meta[1], cnt = s_meta[2];

    if (threadIdx.x < GRP)
        s_tok[threadIdx.x] = (threadIdx.x < cnt) ? g_perm[base + threadIdx.x] : -1;
    __syncthreads();

    for (int i = threadIdx.x; i < ADP * GRP; i += 256) {
        int k = i >> 4, t = i & (GRP - 1);
        int tok = s_tok[t];
        a_sh[k][t] = (tok >= 0) ? g_A[tok * ADP + k] : 0.0f;
    }
    __syncthreads();

    const int o = threadIdx.x;
    float acc[GRP];
#pragma unroll
    for (int t = 0; t < GRP; t++) acc[t] = 0.0f;
    const float4* wr = (const float4*)(Wexp + ((size_t)e * ADP + o) * ADP);
#pragma unroll 4
    for (int k4 = 0; k4 < ADP / 4; k4++) {
        float4 w = wr[k4];
        float wv[4] = {w.x, w.y, w.z, w.w};
#pragma unroll
        for (int j = 0; j < 4; j++) {
            const float4* ap = (const float4*)&a_sh[k4 * 4 + j][0];
#pragma unroll
            for (int t4 = 0; t4 < GRP / 4; t4++) {
                float4 a = ap[t4];
                acc[t4 * 4 + 0] = fmaf(wv[j], a.x, acc[t4 * 4 + 0]);
                acc[t4 * 4 + 1] = fmaf(wv[j], a.y, acc[t4 * 4 + 1]);
                acc[t4 * 4 + 2] = fmaf(wv[j], a.z, acc[t4 * 4 + 2]);
                acc[t4 * 4 + 3] = fmaf(wv[j], a.w, acc[t4 * 4 + 3]);
            }
        }
    }
#pragma unroll
    for (int t = 0; t < GRP; t++) c_sh[t][o] = acc[t];
    __syncthreads();

    const int warp = threadIdx.x >> 5, lane = threadIdx.x & 31;
    for (int t = warp; t < GRP; t += 8) {
        if (t >= cnt) continue;
        float v[8], s = 0.0f;
#pragma unroll
        for (int j = 0; j < 8; j++) { v[j] = c_sh[t][lane + 32 * j]; s += v[j]; }
#pragma unroll
        for (int d = 16; d > 0; d >>= 1) s += __shfl_xor_sync(0xffffffffu, s, d);
        float mu = s * (1.0f / ADP), q = 0.0f;
#pragma unroll
        for (int j = 0; j < 8; j++) { float dd = v[j] - mu; q += dd * dd; }
#pragma unroll
        for (int d = 16; d > 0; d >>= 1) q += __shfl_xor_sync(0xffffffffu, q, d);
        float rs = rsqrtf(q * (1.0f / ADP) + 1e-5f);
        int tok = s_tok[t];
#pragma unroll
        for (int j = 0; j < 8; j++) {
            int oo = lane + 32 * j;
            g_AN[tok * ADP + oo] =
                (v[j] - mu) * rs * gamma[e * ADP + oo] + beta[e * ADP + oo];
        }
    }
}

// ---------------------------------------------------------------------------
// Launch
// ---------------------------------------------------------------------------
extern "C" void kernel_launch(void* const* d_in, const int* in_sizes, int n_in,
                              void* d_out, int out_size) {
    const float* x     = (const float*)d_in[0];
    const float* ew    = (const float*)d_in[1];
    const float* W_up  = (const float*)d_in[2];
    const float* W_ad  = (const float*)d_in[3];
    const float* W_exp = (const float*)d_in[4];
    const float* gamma = (const float*)d_in[5];
    const float* beta  = (const float*)d_in[6];
    const float* W_ep  = (const float*)d_in[7];
    const float* W_out = (const float*)d_in[8];
    float* out = (float*)d_out;

    void *pH, *pA, *pAN, *pWT, *pWc;
    cudaGetSymbolAddress(&pH, g_H);
    cudaGetSymbolAddress(&pA, g_A);
    cudaGetSymbolAddress(&pAN, g_AN);
    cudaGetSymbolAddress(&pWT, g_WepT);
    cudaGetSymbolAddress(&pWc, g_Wc);
    float* H  = (float*)pH;
    float* Aa = (float*)pA;
    float* AN = (float*)pAN;
    float* WT = (float*)pWT;
    float* Wc = (float*)pWc;

    // 1-5: routing prep + Wc precompute (order chosen so launch #6 = big GEMM
    // for ncu -s 5 -c 1 profiling)
    init_kernel<<<1, 32>>>();
    route_kernel<<<(T_TOK + 255) / 256, 256>>>(ew);
    scan_kernel<<<1, 32>>>();
    transpose_kernel<<<dim3(HID / 32, ADP / 32), dim3(32, 8)>>>(W_ep, WT);
    gemm_tf32<2, false><<<dim3(ADP / 128, D_EMB / 128), 256>>>(
        W_out, WT, HID, nullptr, nullptr, 0, Wc, D_EMB, ADP);

    // 6: H = silu(x @ W_up^T)
    gemm_tf32<0, false><<<dim3(HID / 128, T_TOK / 128), 256>>>(
        x, W_up, D_EMB, nullptr, nullptr, 0, H, T_TOK, HID);

    // 7: token scatter (independent of GEMMs)
    scatter_kernel<<<(T_TOK + 255) / 256, 256>>>();

    // 8: A = H @ W_adapt^T
    gemm_tf32<1, false><<<dim3(ADP / 128, T_TOK / 128), 256>>>(
        H, W_ad, HID, nullptr, nullptr, 0, Aa, T_TOK, ADP);

    // 9: adapter + LN -> AN
    adapter_grouped<<<T_TOK / GRP + NEXP, 256>>>(W_exp, gamma, beta);

    // 10: out = [H | AN] @ [W_out | Wc]^T   (K = 4096 + 256)
    gemm_tf32<1, true><<<dim3(D_EMB / 128, T_TOK / 128), 256>>>(
        H, W_out, HID, AN, Wc, ADP, out, T_TOK, D_EMB);
}

// round 5
// speedup vs baseline: 1.7186x; 1.7186x over previous
#include <cuda_runtime.h>
#include <cuda_fp16.h>
#include <math.h>
#include <stdint.h>

#define T_TOK 8192
#define D_EMB 1024
#define HID   4096
#define ADP   256
#define NEXP  8
#define GRP   16

// ---------------- scratch (device globals, allocation-free) ----------------
__device__ __align__(16) float g_H[(size_t)T_TOK * HID];
__device__ __align__(16) float g_A[T_TOK * ADP];
__device__ __align__(16) float g_AN[T_TOK * ADP];    // a_norm / 256
__device__ __align__(16) float g_WepT[ADP * HID];    // W_ep^T [ADP, HID]
__device__ __align__(16) float g_Wc[D_EMB * ADP];    // 25.6 * W_out @ W_ep
__device__ int g_route[T_TOK];
__device__ int g_perm[T_TOK];
__device__ int g_cnt[NEXP];
__device__ int g_cur[NEXP];
__device__ int g_off[NEXP + 1];
__device__ int g_blkoff[NEXP + 1];

// ---------------------------------------------------------------------------
// Routing / grouping
// ---------------------------------------------------------------------------
__global__ void init_kernel() {
    if (threadIdx.x < NEXP) g_cnt[threadIdx.x] = 0;
}
__global__ void route_kernel(const float* __restrict__ ew) {
    int t = blockIdx.x * blockDim.x + threadIdx.x;
    if (t >= T_TOK) return;
    int last = -1;
#pragma unroll
    for (int e = 0; e < NEXP; e++)
        if (ew[t * NEXP + e] > 0.0f) last = e;
    g_route[t] = last;
    if (last >= 0) atomicAdd(&g_cnt[last], 1);
}
__global__ void scan_kernel() {
    if (threadIdx.x == 0) {
        int off = 0, boff = 0;
        g_off[0] = 0; g_blkoff[0] = 0;
        for (int e = 0; e < NEXP; e++) {
            g_cur[e] = 0;
            off += g_cnt[e];                     g_off[e + 1] = off;
            boff += (g_cnt[e] + GRP - 1) / GRP;  g_blkoff[e + 1] = boff;
        }
    }
}
__global__ void scatter_kernel() {
    int t = blockIdx.x * blockDim.x + threadIdx.x;
    if (t >= T_TOK) return;
    int e = g_route[t];
    if (e >= 0) g_perm[g_off[e] + atomicAdd(&g_cur[e], 1)] = t;
}

// ---------------------------------------------------------------------------
// W_ep transpose: [HID, ADP] -> [ADP, HID]
// ---------------------------------------------------------------------------
__global__ void transpose_kernel(const float* __restrict__ in, float* __restrict__ outp) {
    __shared__ float tile[32][33];
    int x = blockIdx.x * 32 + threadIdx.x;
    int y0 = blockIdx.y * 32;
#pragma unroll
    for (int j = 0; j < 32; j += 8)
        tile[threadIdx.y + j][threadIdx.x] = in[(size_t)x * ADP + y0 + threadIdx.y + j];
    __syncthreads();
    int xo = blockIdx.y * 32 + threadIdx.x;
    int yo = blockIdx.x * 32;
#pragma unroll
    for (int j = 0; j < 32; j += 8)
        outp[(size_t)xo * HID + yo + threadIdx.y + j] = tile[threadIdx.x][threadIdx.y + j];
}

// ---------------------------------------------------------------------------
// FP16 mma.sync NT GEMM with ldmatrix.
// C[M,N] = epi( [A0|A1] @ [B0|B1]^T ), K = K0+K1.
//   MODE 0: silu(acc)   MODE 1: acc   MODE 2: escale*acc
// BM=BN=128, BK=32 (halves), 256 thr (8 warps 2x4), warp tile 64x32,
// double buffer, row pitch 40 halves (80B) => conflict-free LDSM.
// ---------------------------------------------------------------------------
#define PITCH 40                    // halves per smem row
#define STG_H (128 * PITCH)         // halves per stage per operand

__device__ __forceinline__ uint32_t smem_u32(const void* p) {
    uint32_t a;
    asm("{ .reg .u64 t; cvta.to.shared.u64 t, %1; cvt.u32.u64 %0, t; }" : "=r"(a) : "l"(p));
    return a;
}
__device__ __forceinline__ uint4 cvt8h(float4 u, float4 v, float s) {
    __half2 h0 = __floats2half2_rn(u.x * s, u.y * s);
    __half2 h1 = __floats2half2_rn(u.z * s, u.w * s);
    __half2 h2 = __floats2half2_rn(v.x * s, v.y * s);
    __half2 h3 = __floats2half2_rn(v.z * s, v.w * s);
    uint4 o;
    o.x = *(uint32_t*)&h0; o.y = *(uint32_t*)&h1;
    o.z = *(uint32_t*)&h2; o.w = *(uint32_t*)&h3;
    return o;
}
__device__ __forceinline__ void ldsm4(uint32_t& r0, uint32_t& r1, uint32_t& r2, uint32_t& r3,
                                      uint32_t addr) {
    asm volatile("ldmatrix.sync.aligned.m8n8.x4.shared.b16 {%0,%1,%2,%3}, [%4];"
                 : "=r"(r0), "=r"(r1), "=r"(r2), "=r"(r3) : "r"(addr));
}
__device__ __forceinline__ void ldsm2(uint32_t& r0, uint32_t& r1, uint32_t addr) {
    asm volatile("ldmatrix.sync.aligned.m8n8.x2.shared.b16 {%0,%1}, [%2];"
                 : "=r"(r0), "=r"(r1) : "r"(addr));
}
__device__ __forceinline__ void mma16(float* d, const uint32_t* a, const uint32_t* b) {
    asm volatile(
        "mma.sync.aligned.m16n8k16.row.col.f32.f16.f16.f32 "
        "{%0,%1,%2,%3}, {%4,%5,%6,%7}, {%8,%9}, {%0,%1,%2,%3};\n"
        : "+f"(d[0]), "+f"(d[1]), "+f"(d[2]), "+f"(d[3])
        : "r"(a[0]), "r"(a[1]), "r"(a[2]), "r"(a[3]), "r"(b[0]), "r"(b[1]));
}

template <int MODE, bool CONCAT>
__global__ void __launch_bounds__(256, 2)
gemm_h(const float* __restrict__ A0, const float* __restrict__ B0, int K0,
       const float* __restrict__ A1, const float* __restrict__ B1, int K1,
       float* __restrict__ C, int M, int N, float sA, float sB, float escale) {
    __shared__ __align__(16) __half As[2][STG_H];
    __shared__ __align__(16) __half Bs[2][STG_H];

    const int tid = threadIdx.x;
    const int lane = tid & 31, warp = tid >> 5;
    const int wm = warp >> 2, wn = warp & 3;          // 2 x 4 warps
    const int g = lane >> 2, c = lane & 3;
    const int m0 = blockIdx.y * 128, n0 = blockIdx.x * 128;

    const int r = tid >> 1;     // tile row 0..127
    const int h = tid & 1;      // k-half (16 floats each)

    // ldmatrix per-lane source coordinates
    const int laneA_row = wm * 64 + (lane & 7) + ((lane >> 3) & 1) * 8;
    const int laneA_chk = lane >> 4;
    const int laneB_row = wn * 32 + (lane & 7);
    const int laneB_chk = (lane >> 3) & 1;

    const uint32_t aBase = smem_u32(&As[0][0]);
    const uint32_t bBase = smem_u32(&Bs[0][0]);

    float acc[4][4][4];
#pragma unroll
    for (int i = 0; i < 4; i++)
#pragma unroll
        for (int j = 0; j < 4; j++)
#pragma unroll
            for (int k = 0; k < 4; k++) acc[i][j][k] = 0.0f;

    const int KT = (K0 + K1) / 32;

    auto ld_tile = [&](int kt, float4* ra, float4* rb) {
        int kg = kt * 32 + h * 16;
        const float* ap;
        const float* bp;
        if (!CONCAT || kg < K0) {
            ap = A0 + (size_t)(m0 + r) * K0 + kg;
            bp = B0 + (size_t)(n0 + r) * K0 + kg;
        } else {
            int kk = kg - K0;
            ap = A1 + (size_t)(m0 + r) * K1 + kk;
            bp = B1 + (size_t)(n0 + r) * K1 + kk;
        }
#pragma unroll
        for (int j = 0; j < 4; j++) {
            ra[j] = *(const float4*)(ap + j * 4);
            rb[j] = *(const float4*)(bp + j * 4);
        }
    };
    auto st_tile = [&](int buf, const float4* ra, const float4* rb) {
        __half* pa = &As[buf][r * PITCH + h * 16];
        __half* pb = &Bs[buf][r * PITCH + h * 16];
        *(uint4*)(pa)     = cvt8h(ra[0], ra[1], sA);
        *(uint4*)(pa + 8) = cvt8h(ra[2], ra[3], sA);
        *(uint4*)(pb)     = cvt8h(rb[0], rb[1], sB);
        *(uint4*)(pb + 8) = cvt8h(rb[2], rb[3], sB);
    };

    {
        float4 ra[4], rb[4];
        ld_tile(0, ra, rb);
        st_tile(0, ra, rb);
    }
    __syncthreads();

    for (int kt = 0; kt < KT; kt++) {
        const int buf = kt & 1;
        float4 ra[4], rb[4];
        if (kt + 1 < KT) ld_tile(kt + 1, ra, rb);

        const uint32_t aStage = aBase + (uint32_t)buf * STG_H * 2;
        const uint32_t bStage = bBase + (uint32_t)buf * STG_H * 2;
#pragma unroll
        for (int ks = 0; ks < 2; ks++) {
            uint32_t af[4][4], bf[4][2];
#pragma unroll
            for (int mi = 0; mi < 4; mi++) {
                uint32_t ad = aStage +
                    (((laneA_row + mi * 16) * PITCH + (ks * 2 + laneA_chk) * 8) << 1);
                ldsm4(af[mi][0], af[mi][1], af[mi][2], af[mi][3], ad);
            }
#pragma unroll
            for (int ni = 0; ni < 4; ni++) {
                uint32_t bd = bStage +
                    (((laneB_row + ni * 8) * PITCH + (ks * 2 + laneB_chk) * 8) << 1);
                ldsm2(bf[ni][0], bf[ni][1], bd);
            }
#pragma unroll
            for (int mi = 0; mi < 4; mi++)
#pragma unroll
                for (int ni = 0; ni < 4; ni++)
                    mma16(acc[mi][ni], af[mi], bf[ni]);
        }

        if (kt + 1 < KT) st_tile(buf ^ 1, ra, rb);
        __syncthreads();
    }

    // epilogue: direct register -> gmem (same fragment map as m16n8k8)
#pragma unroll
    for (int mi = 0; mi < 4; mi++) {
        int row0 = m0 + wm * 64 + mi * 16 + g;
#pragma unroll
        for (int ni = 0; ni < 4; ni++) {
            int col = n0 + wn * 32 + ni * 8 + 2 * c;
            float* p0 = C + (size_t)row0 * N + col;
            float* p1 = C + (size_t)(row0 + 8) * N + col;
            float v0 = acc[mi][ni][0], v1 = acc[mi][ni][1];
            float v2 = acc[mi][ni][2], v3 = acc[mi][ni][3];
            if (MODE == 0) {
                v0 = v0 / (1.0f + __expf(-v0)); v1 = v1 / (1.0f + __expf(-v1));
                v2 = v2 / (1.0f + __expf(-v2)); v3 = v3 / (1.0f + __expf(-v3));
            }
            if (MODE == 2) { v0 *= escale; v1 *= escale; v2 *= escale; v3 *= escale; }
            p0[0] = v0; p0[1] = v1;
            p1[0] = v2; p1[1] = v3;
        }
    }
}

// ---------------------------------------------------------------------------
// Grouped adapter matvec + fused LayerNorm; writes a_norm / 256.
// ---------------------------------------------------------------------------
__global__ void __launch_bounds__(256)
adapter_grouped(const float* __restrict__ Wexp,
                const float* __restrict__ gamma,
                const float* __restrict__ beta) {
    __shared__ float a_sh[ADP][GRP];
    __shared__ float c_sh[GRP][ADP];
    __shared__ int s_tok[GRP];
    __shared__ int s_meta[3];

    const int b = blockIdx.x;
    if (threadIdx.x == 0) {
        int e = 0;
        while (e < NEXP && b >= g_blkoff[e + 1]) e++;
        if (e >= NEXP) s_meta[0] = -1;
        else {
            int base = g_off[e] + (b - g_blkoff[e]) * GRP;
            s_meta[0] = e; s_meta[1] = base;
            s_meta[2] = min(GRP, g_off[e + 1] - base);
        }
    }
    __syncthreads();
    const int e = s_meta[0];
    if (e < 0) return;
    const int base = s_meta[1], cnt = s_meta[2];

    if (threadIdx.x < GRP)
        s_tok[threadIdx.x] = (threadIdx.x < cnt) ? g_perm[base + threadIdx.x] : -1;
    __syncthreads();

    for (int i = threadIdx.x; i < ADP * GRP; i += 256) {
        int k = i >> 4, t = i & (GRP - 1);
        int tok = s_tok[t];
        a_sh[k][t] = (tok >= 0) ? g_A[tok * ADP + k] : 0.0f;
    }
    __syncthreads();

    const int o = threadIdx.x;
    float acc[GRP];
#pragma unroll
    for (int t = 0; t < GRP; t++) acc[t] = 0.0f;
    const float4* wr = (const float4*)(Wexp + ((size_t)e * ADP + o) * ADP);
#pragma unroll 4
    for (int k4 = 0; k4 < ADP / 4; k4++) {
        float4 w = wr[k4];
        float wv[4] = {w.x, w.y, w.z, w.w};
#pragma unroll
        for (int j = 0; j < 4; j++) {
            const float4* ap = (const float4*)&a_sh[k4 * 4 + j][0];
#pragma unroll
            for (int t4 = 0; t4 < GRP / 4; t4++) {
                float4 a = ap[t4];
                acc[t4 * 4 + 0] = fmaf(wv[j], a.x, acc[t4 * 4 + 0]);
                acc[t4 * 4 + 1] = fmaf(wv[j], a.y, acc[t4 * 4 + 1]);
                acc[t4 * 4 + 2] = fmaf(wv[j], a.z, acc[t4 * 4 + 2]);
                acc[t4 * 4 + 3] = fmaf(wv[j], a.w, acc[t4 * 4 + 3]);
            }
        }
    }
#pragma unroll
    for (int t = 0; t < GRP; t++) c_sh[t][o] = acc[t];
    __syncthreads();

    const int warp = threadIdx.x >> 5, lane = threadIdx.x & 31;
    for (int t = warp; t < GRP; t += 8) {
        if (t >= cnt) continue;
        float v[8], s = 0.0f;
#pragma unroll
        for (int j = 0; j < 8; j++) { v[j] = c_sh[t][lane + 32 * j]; s += v[j]; }
#pragma unroll
        for (int d = 16; d > 0; d >>= 1) s += __shfl_xor_sync(0xffffffffu, s, d);
        float mu = s * (1.0f / ADP), q = 0.0f;
#pragma unroll
        for (int j = 0; j < 8; j++) { float dd = v[j] - mu; q += dd * dd; }
#pragma unroll
        for (int d = 16; d > 0; d >>= 1) q += __shfl_xor_sync(0xffffffffu, q, d);
        float rs = rsqrtf(q * (1.0f / ADP) + 1e-5f);
        int tok = s_tok[t];
#pragma unroll
        for (int j = 0; j < 8; j++) {
            int oo = lane + 32 * j;
            g_AN[tok * ADP + oo] =
                ((v[j] - mu) * rs * gamma[e * ADP + oo] + beta[e * ADP + oo]) * (1.0f / 256.0f);
        }
    }
}

// ---------------------------------------------------------------------------
// Launch
// ---------------------------------------------------------------------------
extern "C" void kernel_launch(void* const* d_in, const int* in_sizes, int n_in,
                              void* d_out, int out_size) {
    const float* x     = (const float*)d_in[0];
    const float* ew    = (const float*)d_in[1];
    const float* W_up  = (const float*)d_in[2];
    const float* W_ad  = (const float*)d_in[3];
    const float* W_exp = (const float*)d_in[4];
    const float* gamma = (const float*)d_in[5];
    const float* beta  = (const float*)d_in[6];
    const float* W_ep  = (const float*)d_in[7];
    const float* W_out = (const float*)d_in[8];
    float* out = (float*)d_out;

    void *pH, *pA, *pAN, *pWT, *pWc;
    cudaGetSymbolAddress(&pH, g_H);
    cudaGetSymbolAddress(&pA, g_A);
    cudaGetSymbolAddress(&pAN, g_AN);
    cudaGetSymbolAddress(&pWT, g_WepT);
    cudaGetSymbolAddress(&pWc, g_Wc);
    float* H  = (float*)pH;
    float* Aa = (float*)pA;
    float* AN = (float*)pAN;
    float* WT = (float*)pWT;
    float* Wc = (float*)pWc;

    // 1-5: prep (launch #6 is the big GEMM => profiled by ncu -s 5 -c 1)
    init_kernel<<<1, 32>>>();
    route_kernel<<<(T_TOK + 255) / 256, 256>>>(ew);
    scan_kernel<<<1, 32>>>();
    transpose_kernel<<<dim3(HID / 32, ADP / 32), dim3(32, 8)>>>(W_ep, WT);
    // Wc = 25.6 * W_out @ W_ep ; inputs prescaled x32 (fp16 range), epi 25.6/1024
    gemm_h<2, false><<<dim3(ADP / 128, D_EMB / 128), 256>>>(
        W_out, WT, HID, nullptr, nullptr, 0, Wc, D_EMB, ADP,
        32.0f, 32.0f, 25.6f / 1024.0f);

    // 6: H = silu(x @ W_up^T)
    gemm_h<0, false><<<dim3(HID / 128, T_TOK / 128), 256>>>(
        x, W_up, D_EMB, nullptr, nullptr, 0, H, T_TOK, HID, 1.0f, 1.0f, 1.0f);

    // 7: token scatter
    scatter_kernel<<<(T_TOK + 255) / 256, 256>>>();

    // 8: A = H @ W_adapt^T
    gemm_h<1, false><<<dim3(ADP / 128, T_TOK / 128), 256>>>(
        H, W_ad, HID, nullptr, nullptr, 0, Aa, T_TOK, ADP, 1.0f, 1.0f, 1.0f);

    // 9: adapter + LN -> AN (= a_norm/256)
    adapter_grouped<<<T_TOK / GRP + NEXP, 256>>>(W_exp, gamma, beta);

    // 10: out = [H | AN] @ [W_out | Wc]^T  (K = 4096+256); 0.1 = 25.6/256 exact
    gemm_h<1, true><<<dim3(D_EMB / 128, T_TOK / 128), 256>>>(
        H, W_out, HID, AN, Wc, ADP, out, T_TOK, D_EMB, 1.0f, 1.0f, 1.0f);
}

// round 6
// speedup vs baseline: 2.6994x; 1.5707x over previous
#include <cuda_runtime.h>
#include <cuda_fp16.h>
#include <math.h>
#include <stdint.h>

#define T_TOK 8192
#define D_EMB 1024
#define HID   4096
#define ADP   256
#define NEXP  8
#define GRP   16

// ---------------- scratch (device globals, allocation-free) ----------------
__device__ __align__(16) __half g_xh[(size_t)T_TOK * D_EMB];
__device__ __align__(16) __half g_Wuph[(size_t)HID * D_EMB];
__device__ __align__(16) __half g_Wadh[ADP * HID];
__device__ __align__(16) __half g_Wouth[(size_t)D_EMB * HID];  // 32 * W_out
__device__ __align__(16) __half g_WepTh[ADP * HID];            // 32 * W_ep^T
__device__ __align__(16) __half g_Wch[D_EMB * ADP];            // 1024 * W_out@W_ep
__device__ __align__(16) __half g_Hh[(size_t)T_TOK * HID];     // silu(x@W_up^T), fp16
__device__ __align__(16) float  g_A[T_TOK * ADP];
__device__ __align__(16) __half g_ANh[T_TOK * ADP];            // a_norm / 320
__device__ int g_route[T_TOK];
__device__ int g_perm[T_TOK];
__device__ int g_cnt[NEXP];
__device__ int g_cur[NEXP];
__device__ int g_off[NEXP + 1];
__device__ int g_blkoff[NEXP + 1];

// ---------------------------------------------------------------------------
// fp32 -> fp16 convert (scaled), 8 elems/thread
// ---------------------------------------------------------------------------
__global__ void cvt_kernel(const float* __restrict__ in, __half* __restrict__ outp,
                           int n, float scale) {
    int i = (blockIdx.x * blockDim.x + threadIdx.x) * 8;
    if (i >= n) return;
    float4 a = *(const float4*)(in + i);
    float4 b = *(const float4*)(in + i + 4);
    __half2 h0 = __floats2half2_rn(a.x * scale, a.y * scale);
    __half2 h1 = __floats2half2_rn(a.z * scale, a.w * scale);
    __half2 h2 = __floats2half2_rn(b.x * scale, b.y * scale);
    __half2 h3 = __floats2half2_rn(b.z * scale, b.w * scale);
    uint4 o;
    o.x = *(uint32_t*)&h0; o.y = *(uint32_t*)&h1;
    o.z = *(uint32_t*)&h2; o.w = *(uint32_t*)&h3;
    *(uint4*)(outp + i) = o;
}

// ---------------------------------------------------------------------------
// W_ep transpose + convert: [HID, ADP] f32 -> [ADP, HID] f16 * 32
// ---------------------------------------------------------------------------
__global__ void transpose_cvt_kernel(const float* __restrict__ in, __half* __restrict__ outp) {
    __shared__ float tile[32][33];
    int x = blockIdx.x * 32 + threadIdx.x;   // HID
    int y0 = blockIdx.y * 32;                // ADP
#pragma unroll
    for (int j = 0; j < 32; j += 8)
        tile[threadIdx.y + j][threadIdx.x] = in[(size_t)x * ADP + y0 + threadIdx.y + j];
    __syncthreads();
    int xo = blockIdx.y * 32 + threadIdx.x;  // ADP
    int yo = blockIdx.x * 32;                // HID
#pragma unroll
    for (int j = 0; j < 32; j += 8)
        outp[(size_t)xo * HID + yo + threadIdx.y + j] =
            __float2half(tile[threadIdx.x][threadIdx.y + j] * 32.0f);
}

// ---------------------------------------------------------------------------
// Routing / grouping
// ---------------------------------------------------------------------------
__global__ void init_kernel() {
    if (threadIdx.x < NEXP) g_cnt[threadIdx.x] = 0;
}
__global__ void route_kernel(const float* __restrict__ ew) {
    int t = blockIdx.x * blockDim.x + threadIdx.x;
    if (t >= T_TOK) return;
    int last = -1;
#pragma unroll
    for (int e = 0; e < NEXP; e++)
        if (ew[t * NEXP + e] > 0.0f) last = e;
    g_route[t] = last;
    if (last >= 0) atomicAdd(&g_cnt[last], 1);
}
__global__ void scan_kernel() {
    if (threadIdx.x == 0) {
        int off = 0, boff = 0;
        g_off[0] = 0; g_blkoff[0] = 0;
        for (int e = 0; e < NEXP; e++) {
            g_cur[e] = 0;
            off += g_cnt[e];                     g_off[e + 1] = off;
            boff += (g_cnt[e] + GRP - 1) / GRP;  g_blkoff[e + 1] = boff;
        }
    }
}
__global__ void scatter_kernel() {
    int t = blockIdx.x * blockDim.x + threadIdx.x;
    if (t >= T_TOK) return;
    int e = g_route[t];
    if (e >= 0) g_perm[g_off[e] + atomicAdd(&g_cur[e], 1)] = t;
}

// ---------------------------------------------------------------------------
// FP16 mma.sync NT GEMM, cp.async 3-stage pipeline, ldmatrix.
// C[M,N] = epi( [A0|A1] @ [B0|B1]^T ), operands fp16 in gmem, K = K0+K1.
//   MODE 0: silu   MODE 1: acc   MODE 2: escale*acc
//   OUT_HALF: store __half, else float.
// BM=BN=128, BK=32, 256 thr (8 warps 2x4), warp tile 64x32, pitch 40 halves.
// ---------------------------------------------------------------------------
#define PITCH 40
#define STG_BYTES (128 * PITCH * 2)   // 10240 B per operand per stage
#define NSTG 3
#define SMEM_TOTAL (2 * NSTG * STG_BYTES)   // 61440

__device__ __forceinline__ uint32_t smem_u32(const void* p) {
    uint32_t a;
    asm("{ .reg .u64 t; cvta.to.shared.u64 t, %1; cvt.u32.u64 %0, t; }" : "=r"(a) : "l"(p));
    return a;
}
__device__ __forceinline__ void cp16(uint32_t dst, const void* src) {
    asm volatile("cp.async.cg.shared.global [%0], [%1], 16;" :: "r"(dst), "l"(src));
}
__device__ __forceinline__ void cp_commit() {
    asm volatile("cp.async.commit_group;");
}
template <int N>
__device__ __forceinline__ void cp_wait() {
    asm volatile("cp.async.wait_group %0;" :: "n"(N));
}
__device__ __forceinline__ void ldsm4(uint32_t& r0, uint32_t& r1, uint32_t& r2, uint32_t& r3,
                                      uint32_t addr) {
    asm volatile("ldmatrix.sync.aligned.m8n8.x4.shared.b16 {%0,%1,%2,%3}, [%4];"
                 : "=r"(r0), "=r"(r1), "=r"(r2), "=r"(r3) : "r"(addr));
}
__device__ __forceinline__ void ldsm2(uint32_t& r0, uint32_t& r1, uint32_t addr) {
    asm volatile("ldmatrix.sync.aligned.m8n8.x2.shared.b16 {%0,%1}, [%2];"
                 : "=r"(r0), "=r"(r1) : "r"(addr));
}
__device__ __forceinline__ void mma16(float* d, const uint32_t* a, const uint32_t* b) {
    asm volatile(
        "mma.sync.aligned.m16n8k16.row.col.f32.f16.f16.f32 "
        "{%0,%1,%2,%3}, {%4,%5,%6,%7}, {%8,%9}, {%0,%1,%2,%3};\n"
        : "+f"(d[0]), "+f"(d[1]), "+f"(d[2]), "+f"(d[3])
        : "r"(a[0]), "r"(a[1]), "r"(a[2]), "r"(a[3]), "r"(b[0]), "r"(b[1]));
}

template <int MODE, bool CONCAT, bool OUT_HALF>
__global__ void __launch_bounds__(256, 2)
gemm_h(const __half* __restrict__ A0, const __half* __restrict__ B0, int K0,
       const __half* __restrict__ A1, const __half* __restrict__ B1, int K1,
       void* __restrict__ Cv, int M, int N, float escale) {
    extern __shared__ __align__(16) char smem[];
    const uint32_t aBase = smem_u32(smem);
    const uint32_t bBase = aBase + NSTG * STG_BYTES;

    const int tid = threadIdx.x;
    const int lane = tid & 31, warp = tid >> 5;
    const int wm = warp >> 2, wn = warp & 3;
    const int g = lane >> 2, c = lane & 3;
    const int m0 = blockIdx.y * 128, n0 = blockIdx.x * 128;

    const int r = tid >> 1;     // row 0..127
    const int h = tid & 1;      // k-half (16 halves)

    const int laneA_row = wm * 64 + (lane & 7) + ((lane >> 3) & 1) * 8;
    const int laneA_chk = lane >> 4;
    const int laneB_row = wn * 32 + (lane & 7);
    const int laneB_chk = (lane >> 3) & 1;

    const uint32_t dA = aBase + (r * PITCH + h * 16) * 2;
    const uint32_t dB = bBase + (r * PITCH + h * 16) * 2;

    float acc[4][4][4];
#pragma unroll
    for (int i = 0; i < 4; i++)
#pragma unroll
        for (int j = 0; j < 4; j++)
#pragma unroll
            for (int k = 0; k < 4; k++) acc[i][j][k] = 0.0f;

    const int KT = (K0 + K1) / 32;

    auto issue = [&](int kt, int s) {
        int kg = kt * 32 + h * 16;
        const __half* ap;
        const __half* bp;
        if (!CONCAT || kg < K0) {
            ap = A0 + (size_t)(m0 + r) * K0 + kg;
            bp = B0 + (size_t)(n0 + r) * K0 + kg;
        } else {
            int kk = kg - K0;
            ap = A1 + (size_t)(m0 + r) * K1 + kk;
            bp = B1 + (size_t)(n0 + r) * K1 + kk;
        }
        uint32_t da = dA + s * STG_BYTES;
        uint32_t db = dB + s * STG_BYTES;
        cp16(da, ap);       cp16(da + 16, ap + 8);
        cp16(db, bp);       cp16(db + 16, bp + 8);
    };

    // prologue: stages 0, 1
    issue(0, 0); cp_commit();
    if (1 < KT) { issue(1, 1); cp_commit(); }

    for (int kt = 0; kt < KT; kt++) {
        const int s = kt % NSTG;
        if (kt + 1 < KT) cp_wait<1>(); else cp_wait<0>();
        __syncthreads();

        const uint32_t aStage = aBase + s * STG_BYTES;
        const uint32_t bStage = bBase + s * STG_BYTES;
#pragma unroll
        for (int ks = 0; ks < 2; ks++) {
            uint32_t af[4][4], bf[4][2];
#pragma unroll
            for (int mi = 0; mi < 4; mi++) {
                uint32_t ad = aStage +
                    (((laneA_row + mi * 16) * PITCH + (ks * 2 + laneA_chk) * 8) << 1);
                ldsm4(af[mi][0], af[mi][1], af[mi][2], af[mi][3], ad);
            }
#pragma unroll
            for (int ni = 0; ni < 4; ni++) {
                uint32_t bd = bStage +
                    (((laneB_row + ni * 8) * PITCH + (ks * 2 + laneB_chk) * 8) << 1);
                ldsm2(bf[ni][0], bf[ni][1], bd);
            }
#pragma unroll
            for (int mi = 0; mi < 4; mi++)
#pragma unroll
                for (int ni = 0; ni < 4; ni++)
                    mma16(acc[mi][ni], af[mi], bf[ni]);
        }

        if (kt + 2 < KT) { issue(kt + 2, (kt + 2) % NSTG); cp_commit(); }
        else { cp_commit(); }   // keep group accounting uniform
        __syncthreads();
    }

    // epilogue
#pragma unroll
    for (int mi = 0; mi < 4; mi++) {
        int row0 = m0 + wm * 64 + mi * 16 + g;
#pragma unroll
        for (int ni = 0; ni < 4; ni++) {
            int col = n0 + wn * 32 + ni * 8 + 2 * c;
            float v0 = acc[mi][ni][0], v1 = acc[mi][ni][1];
            float v2 = acc[mi][ni][2], v3 = acc[mi][ni][3];
            if (MODE == 0) {
                v0 = v0 / (1.0f + __expf(-v0)); v1 = v1 / (1.0f + __expf(-v1));
                v2 = v2 / (1.0f + __expf(-v2)); v3 = v3 / (1.0f + __expf(-v3));
            }
            if (MODE == 2) { v0 *= escale; v1 *= escale; v2 *= escale; v3 *= escale; }
            if (OUT_HALF) {
                __half* Ch = (__half*)Cv;
                *(__half2*)(Ch + (size_t)row0 * N + col)       = __floats2half2_rn(v0, v1);
                *(__half2*)(Ch + (size_t)(row0 + 8) * N + col) = __floats2half2_rn(v2, v3);
            } else {
                float* Cf = (float*)Cv;
                float* p0 = Cf + (size_t)row0 * N + col;
                float* p1 = Cf + (size_t)(row0 + 8) * N + col;
                p0[0] = v0; p0[1] = v1;
                p1[0] = v2; p1[1] = v3;
            }
        }
    }
}

// ---------------------------------------------------------------------------
// Grouped adapter matvec + fused LayerNorm; writes (a_norm / 320) as fp16.
// ---------------------------------------------------------------------------
__global__ void __launch_bounds__(256)
adapter_grouped(const float* __restrict__ Wexp,
                const float* __restrict__ gamma,
                const float* __restrict__ beta) {
    __shared__ float a_sh[ADP][GRP];
    __shared__ float c_sh[GRP][ADP];
    __shared__ int s_tok[GRP];
    __shared__ int s_meta[3];

    const int b = blockIdx.x;
    if (threadIdx.x == 0) {
        int e = 0;
        while (e < NEXP && b >= g_blkoff[e + 1]) e++;
        if (e >= NEXP) s_meta[0] = -1;
        else {
            int base = g_off[e] + (b - g_blkoff[e]) * GRP;
            s_meta[0] = e; s_meta[1] = base;
            s_meta[2] = min(GRP, g_off[e + 1] - base);
        }
    }
    __syncthreads();
    const int e = s_meta[0];
    if (e < 0) return;
    const int base = s_meta[1], cnt = s_meta[2];

    if (threadIdx.x < GRP)
        s_tok[threadIdx.x] = (threadIdx.x < cnt) ? g_perm[base + threadIdx.x] : -1;
    __syncthreads();

    for (int i = threadIdx.x; i < ADP * GRP; i += 256) {
        int k = i >> 4, t = i & (GRP - 1);
        int tok = s_tok[t];
        a_sh[k][t] = (tok >= 0) ? g_A[tok * ADP + k] : 0.0f;
    }
    __syncthreads();

    const int o = threadIdx.x;
    float acc[GRP];
#pragma unroll
    for (int t = 0; t < GRP; t++) acc[t] = 0.0f;
    const float4* wr = (const float4*)(Wexp + ((size_t)e * ADP + o) * ADP);
#pragma unroll 4
    for (int k4 = 0; k4 < ADP / 4; k4++) {
        float4 w = wr[k4];
        float wv[4] = {w.x, w.y, w.z, w.w};
#pragma unroll
        for (int j = 0; j < 4; j++) {
            const float4* ap = (const float4*)&a_sh[k4 * 4 + j][0];
#pragma unroll
            for (int t4 = 0; t4 < GRP / 4; t4++) {
                float4 a = ap[t4];
                acc[t4 * 4 + 0] = fmaf(wv[j], a.x, acc[t4 * 4 + 0]);
                acc[t4 * 4 + 1] = fmaf(wv[j], a.y, acc[t4 * 4 + 1]);
                acc[t4 * 4 + 2] = fmaf(wv[j], a.z, acc[t4 * 4 + 2]);
                acc[t4 * 4 + 3] = fmaf(wv[j], a.w, acc[t4 * 4 + 3]);
            }
        }
    }
#pragma unroll
    for (int t = 0; t < GRP; t++) c_sh[t][o] = acc[t];
    __syncthreads();

    const int warp = threadIdx.x >> 5, lane = threadIdx.x & 31;
    for (int t = warp; t < GRP; t += 8) {
        if (t >= cnt) continue;
        float v[8], s = 0.0f;
#pragma unroll
        for (int j = 0; j < 8; j++) { v[j] = c_sh[t][lane + 32 * j]; s += v[j]; }
#pragma unroll
        for (int d = 16; d > 0; d >>= 1) s += __shfl_xor_sync(0xffffffffu, s, d);
        float mu = s * (1.0f / ADP), q = 0.0f;
#pragma unroll
        for (int j = 0; j < 8; j++) { float dd = v[j] - mu; q += dd * dd; }
#pragma unroll
        for (int d = 16; d > 0; d >>= 1) q += __shfl_xor_sync(0xffffffffu, q, d);
        float rs = rsqrtf(q * (1.0f / ADP) + 1e-5f);
        int tok = s_tok[t];
#pragma unroll
        for (int j = 0; j < 8; j++) {
            int oo = lane + 32 * j;
            float val = ((v[j] - mu) * rs * gamma[e * ADP + oo] + beta[e * ADP + oo])
                        * (1.0f / 320.0f);
            g_ANh[tok * ADP + oo] = __float2half(val);
        }
    }
}

// ---------------------------------------------------------------------------
// Launch
// ---------------------------------------------------------------------------
extern "C" void kernel_launch(void* const* d_in, const int* in_sizes, int n_in,
                              void* d_out, int out_size) {
    const float* x     = (const float*)d_in[0];
    const float* ew    = (const float*)d_in[1];
    const float* W_up  = (const float*)d_in[2];
    const float* W_ad  = (const float*)d_in[3];
    const float* W_exp = (const float*)d_in[4];
    const float* gamma = (const float*)d_in[5];
    const float* beta  = (const float*)d_in[6];
    const float* W_ep  = (const float*)d_in[7];
    const float* W_out = (const float*)d_in[8];
    float* out = (float*)d_out;

    void *pxh, *pWuph, *pWadh, *pWouth, *pWepTh, *pWch, *pHh, *pA, *pANh;
    cudaGetSymbolAddress(&pxh, g_xh);
    cudaGetSymbolAddress(&pWuph, g_Wuph);
    cudaGetSymbolAddress(&pWadh, g_Wadh);
    cudaGetSymbolAddress(&pWouth, g_Wouth);
    cudaGetSymbolAddress(&pWepTh, g_WepTh);
    cudaGetSymbolAddress(&pWch, g_Wch);
    cudaGetSymbolAddress(&pHh, g_Hh);
    cudaGetSymbolAddress(&pA, g_A);
    cudaGetSymbolAddress(&pANh, g_ANh);
    __half* xh     = (__half*)pxh;
    __half* Wuph   = (__half*)pWuph;
    __half* Wadh   = (__half*)pWadh;
    __half* Wouth  = (__half*)pWouth;
    __half* WepTh  = (__half*)pWepTh;
    __half* Wch    = (__half*)pWch;
    __half* Hh     = (__half*)pHh;
    float*  Aa     = (float*)pA;
    __half* ANh    = (__half*)pANh;

    cudaFuncSetAttribute(gemm_h<0, false, true>,  cudaFuncAttributeMaxDynamicSharedMemorySize, SMEM_TOTAL);
    cudaFuncSetAttribute(gemm_h<1, false, false>, cudaFuncAttributeMaxDynamicSharedMemorySize, SMEM_TOTAL);
    cudaFuncSetAttribute(gemm_h<1, false, true>,  cudaFuncAttributeMaxDynamicSharedMemorySize, SMEM_TOTAL);
    cudaFuncSetAttribute(gemm_h<2, true, false>,  cudaFuncAttributeMaxDynamicSharedMemorySize, SMEM_TOTAL);

    // 1-3: converts needed by the big GEMM
    cvt_kernel<<<T_TOK * D_EMB / 8 / 256, 256>>>(x, xh, T_TOK * D_EMB, 1.0f);
    cvt_kernel<<<HID * D_EMB / 8 / 256, 256>>>(W_up, Wuph, HID * D_EMB, 1.0f);
    init_kernel<<<1, 32>>>();

    // 4: H = silu(x @ W_up^T) -> fp16   (profiled launch)
    gemm_h<0, false, true><<<dim3(HID / 128, T_TOK / 128), 256, SMEM_TOTAL>>>(
        xh, Wuph, D_EMB, nullptr, nullptr, 0, Hh, T_TOK, HID, 1.0f);

    // 5-10: routing + remaining converts + Wc precompute
    route_kernel<<<(T_TOK + 255) / 256, 256>>>(ew);
    scan_kernel<<<1, 32>>>();
    cvt_kernel<<<ADP * HID / 8 / 256, 256>>>(W_ad, Wadh, ADP * HID, 1.0f);
    cvt_kernel<<<D_EMB * HID / 8 / 256, 256>>>(W_out, Wouth, D_EMB * HID, 32.0f);
    transpose_cvt_kernel<<<dim3(HID / 32, ADP / 32), dim3(32, 8)>>>(W_ep, WepTh);
    // Wc_h = (32 W_out) @ (32 W_ep) = 1024 * W_out@W_ep  -> fp16
    gemm_h<1, false, true><<<dim3(ADP / 128, D_EMB / 128), 256, SMEM_TOTAL>>>(
        Wouth, WepTh, HID, nullptr, nullptr, 0, Wch, D_EMB, ADP, 1.0f);

    // 11: scatter
    scatter_kernel<<<(T_TOK + 255) / 256, 256>>>();

    // 12: A = H @ W_adapt^T  (fp32 out for adapter)
    gemm_h<1, false, false><<<dim3(ADP / 128, T_TOK / 128), 256, SMEM_TOTAL>>>(
        Hh, Wadh, HID, nullptr, nullptr, 0, Aa, T_TOK, ADP, 1.0f);

    // 13: adapter + LN -> ANh (= a_norm/320)
    adapter_grouped<<<T_TOK / GRP + NEXP, 256>>>(W_exp, gamma, beta);

    // 14: out = (1/32) * [H | ANh] @ [32W_out | 1024Wc]^T
    //     shared: 32/32 = 1 ; expert: 1024/(320*32) = 0.1  (exact)
    gemm_h<2, true, false><<<dim3(D_EMB / 128, T_TOK / 128), 256, SMEM_TOTAL>>>(
        Hh, Wouth, HID, ANh, Wch, ADP, out, T_TOK, D_EMB, 1.0f / 32.0f);
}

// round 7
// speedup vs baseline: 2.7947x; 1.0353x over previous
#include <cuda_runtime.h>
#include <cuda_fp16.h>
#include <math.h>
#include <stdint.h>

#define T_TOK 8192
#define D_EMB 1024
#define HID   4096
#define ADP   256
#define NEXP  8
#define GRP   16

// ---------------- scratch (device globals, allocation-free) ----------------
__device__ __align__(16) __half g_xh[(size_t)T_TOK * D_EMB];
__device__ __align__(16) __half g_Wuph[(size_t)HID * D_EMB];
__device__ __align__(16) __half g_Wadh[ADP * HID];
__device__ __align__(16) __half g_Wouth[(size_t)D_EMB * HID];  // 32 * W_out
__device__ __align__(16) __half g_WepTh[ADP * HID];            // 32 * W_ep^T
__device__ __align__(16) __half g_Wch[D_EMB * ADP];            // 1024 * W_out@W_ep
__device__ __align__(16) __half g_Hh[(size_t)T_TOK * HID];     // silu(x@W_up^T), fp16
__device__ __align__(16) float  g_A[T_TOK * ADP];
__device__ __align__(16) __half g_ANh[T_TOK * ADP];            // a_norm / 320
__device__ int g_route[T_TOK];
__device__ int g_perm[T_TOK];
__device__ int g_cnt[NEXP];
__device__ int g_cur[NEXP];
__device__ int g_off[NEXP + 1];
__device__ int g_blkoff[NEXP + 1];

// ---------------------------------------------------------------------------
// fp32 -> fp16 convert (scaled), 8 elems/thread
// ---------------------------------------------------------------------------
__global__ void cvt_kernel(const float* __restrict__ in, __half* __restrict__ outp,
                           int n, float scale) {
    int i = (blockIdx.x * blockDim.x + threadIdx.x) * 8;
    if (i >= n) return;
    float4 a = *(const float4*)(in + i);
    float4 b = *(const float4*)(in + i + 4);
    __half2 h0 = __floats2half2_rn(a.x * scale, a.y * scale);
    __half2 h1 = __floats2half2_rn(a.z * scale, a.w * scale);
    __half2 h2 = __floats2half2_rn(b.x * scale, b.y * scale);
    __half2 h3 = __floats2half2_rn(b.z * scale, b.w * scale);
    uint4 o;
    o.x = *(uint32_t*)&h0; o.y = *(uint32_t*)&h1;
    o.z = *(uint32_t*)&h2; o.w = *(uint32_t*)&h3;
    *(uint4*)(outp + i) = o;
}

// ---------------------------------------------------------------------------
// W_ep transpose + convert: [HID, ADP] f32 -> [ADP, HID] f16 * 32
// ---------------------------------------------------------------------------
__global__ void transpose_cvt_kernel(const float* __restrict__ in, __half* __restrict__ outp) {
    __shared__ float tile[32][33];
    int x = blockIdx.x * 32 + threadIdx.x;
    int y0 = blockIdx.y * 32;
#pragma unroll
    for (int j = 0; j < 32; j += 8)
        tile[threadIdx.y + j][threadIdx.x] = in[(size_t)x * ADP + y0 + threadIdx.y + j];
    __syncthreads();
    int xo = blockIdx.y * 32 + threadIdx.x;
    int yo = blockIdx.x * 32;
#pragma unroll
    for (int j = 0; j < 32; j += 8)
        outp[(size_t)xo * HID + yo + threadIdx.y + j] =
            __float2half(tile[threadIdx.x][threadIdx.y + j] * 32.0f);
}

// ---------------------------------------------------------------------------
// Routing / grouping
// ---------------------------------------------------------------------------
__global__ void init_kernel() {
    if (threadIdx.x < NEXP) g_cnt[threadIdx.x] = 0;
}
__global__ void route_kernel(const float* __restrict__ ew) {
    int t = blockIdx.x * blockDim.x + threadIdx.x;
    if (t >= T_TOK) return;
    int last = -1;
#pragma unroll
    for (int e = 0; e < NEXP; e++)
        if (ew[t * NEXP + e] > 0.0f) last = e;
    g_route[t] = last;
    if (last >= 0) atomicAdd(&g_cnt[last], 1);
}
__global__ void scan_kernel() {
    if (threadIdx.x == 0) {
        int off = 0, boff = 0;
        g_off[0] = 0; g_blkoff[0] = 0;
        for (int e = 0; e < NEXP; e++) {
            g_cur[e] = 0;
            off += g_cnt[e];                     g_off[e + 1] = off;
            boff += (g_cnt[e] + GRP - 1) / GRP;  g_blkoff[e + 1] = boff;
        }
    }
}
__global__ void scatter_kernel() {
    int t = blockIdx.x * blockDim.x + threadIdx.x;
    if (t >= T_TOK) return;
    int e = g_route[t];
    if (e >= 0) g_perm[g_off[e] + atomicAdd(&g_cur[e], 1)] = t;
}

// ---------------------------------------------------------------------------
// FP16 mma.sync NT GEMM, 4-stage cp.async ring, single barrier per k-tile,
// ldmatrix.x4 for both operands.
// C[M,N] = epi( [A0|A1] @ [B0|B1]^T ), operands fp16 in gmem, K = K0+K1.
//   MODE 0: silu   MODE 1: acc   MODE 2: escale*acc
// BM=BN=128, BK=32, 256 thr (8 warps 2x4), warp tile 64x32, pitch 40 halves.
// ---------------------------------------------------------------------------
#define PITCH 40
#define STG_BYTES (128 * PITCH * 2)          // 10240 B / operand / stage
#define NSTG 4
#define SMEM_TOTAL (2 * NSTG * STG_BYTES)    // 81920

__device__ __forceinline__ uint32_t smem_u32(const void* p) {
    uint32_t a;
    asm("{ .reg .u64 t; cvta.to.shared.u64 t, %1; cvt.u32.u64 %0, t; }" : "=r"(a) : "l"(p));
    return a;
}
__device__ __forceinline__ void cp16(uint32_t dst, const void* src) {
    asm volatile("cp.async.cg.shared.global [%0], [%1], 16;" :: "r"(dst), "l"(src));
}
__device__ __forceinline__ void cp_commit() {
    asm volatile("cp.async.commit_group;");
}
template <int N>
__device__ __forceinline__ void cp_wait() {
    asm volatile("cp.async.wait_group %0;" :: "n"(N));
}
__device__ __forceinline__ void ldsm4(uint32_t& r0, uint32_t& r1, uint32_t& r2, uint32_t& r3,
                                      uint32_t addr) {
    asm volatile("ldmatrix.sync.aligned.m8n8.x4.shared.b16 {%0,%1,%2,%3}, [%4];"
                 : "=r"(r0), "=r"(r1), "=r"(r2), "=r"(r3) : "r"(addr));
}
__device__ __forceinline__ void mma16(float* d, const uint32_t* a, const uint32_t* b) {
    asm volatile(
        "mma.sync.aligned.m16n8k16.row.col.f32.f16.f16.f32 "
        "{%0,%1,%2,%3}, {%4,%5,%6,%7}, {%8,%9}, {%0,%1,%2,%3};\n"
        : "+f"(d[0]), "+f"(d[1]), "+f"(d[2]), "+f"(d[3])
        : "r"(a[0]), "r"(a[1]), "r"(a[2]), "r"(a[3]), "r"(b[0]), "r"(b[1]));
}

template <int MODE, bool CONCAT, bool OUT_HALF>
__global__ void __launch_bounds__(256, 2)
gemm_h(const __half* __restrict__ A0, const __half* __restrict__ B0, int K0,
       const __half* __restrict__ A1, const __half* __restrict__ B1, int K1,
       void* __restrict__ Cv, int M, int N, float escale) {
    extern __shared__ __align__(16) char smem[];
    const uint32_t aBase = smem_u32(smem);
    const uint32_t bBase = aBase + NSTG * STG_BYTES;

    const int tid = threadIdx.x;
    const int lane = tid & 31, warp = tid >> 5;
    const int wm = warp >> 2, wn = warp & 3;
    const int g = lane >> 2, c = lane & 3;
    const int m0 = blockIdx.y * 128, n0 = blockIdx.x * 128;

    const int r = tid >> 1;     // row 0..127
    const int h = tid & 1;      // k-half (16 halves)

    // ldmatrix lane->address maps
    const int laneA_row = wm * 64 + (lane & 7) + ((lane >> 3) & 1) * 8;
    const int laneA_chk = lane >> 4;
    const int laneB_row = wn * 32 + (lane & 7) + ((lane >> 4) & 1) * 8;  // x4: 2 ni per op
    const int laneB_chk = (lane >> 3) & 1;

    const uint32_t dA = aBase + (r * PITCH + h * 16) * 2;
    const uint32_t dB = bBase + (r * PITCH + h * 16) * 2;

    float acc[4][4][4];
#pragma unroll
    for (int i = 0; i < 4; i++)
#pragma unroll
        for (int j = 0; j < 4; j++)
#pragma unroll
            for (int k = 0; k < 4; k++) acc[i][j][k] = 0.0f;

    const int KT = (K0 + K1) / 32;

    auto issue = [&](int kt, int s) {
        int kg = kt * 32 + h * 16;
        const __half* ap;
        const __half* bp;
        if (!CONCAT || kg < K0) {
            ap = A0 + (size_t)(m0 + r) * K0 + kg;
            bp = B0 + (size_t)(n0 + r) * K0 + kg;
        } else {
            int kk = kg - K0;
            ap = A1 + (size_t)(m0 + r) * K1 + kk;
            bp = B1 + (size_t)(n0 + r) * K1 + kk;
        }
        uint32_t da = dA + s * STG_BYTES;
        uint32_t db = dB + s * STG_BYTES;
        cp16(da, ap);       cp16(da + 16, ap + 8);
        cp16(db, bp);       cp16(db + 16, bp + 8);
    };

    // prologue: stages 0..2
    issue(0, 0); cp_commit();
    issue(1, 1); cp_commit();
    issue(2, 2); cp_commit();

    for (int kt = 0; kt < KT; kt++) {
        const int s = kt & (NSTG - 1);
        cp_wait<2>();
        __syncthreads();   // single barrier per k-tile (stage (kt+3)%4 was last
                           // read at iter kt-1; all reads precede this barrier)

        const uint32_t aStage = aBase + s * STG_BYTES;
        const uint32_t bStage = bBase + s * STG_BYTES;
#pragma unroll
        for (int ks = 0; ks < 2; ks++) {
            uint32_t af[4][4], bf[4][2];
#pragma unroll
            for (int mi = 0; mi < 4; mi++) {
                uint32_t ad = aStage +
                    (((laneA_row + mi * 16) * PITCH + (ks * 2 + laneA_chk) * 8) << 1);
                ldsm4(af[mi][0], af[mi][1], af[mi][2], af[mi][3], ad);
            }
#pragma unroll
            for (int np = 0; np < 2; np++) {   // each ldsm4 fills 2 ni fragments
                uint32_t bd = bStage +
                    (((laneB_row + np * 16) * PITCH + (ks * 2 + laneB_chk) * 8) << 1);
                ldsm4(bf[np * 2][0], bf[np * 2][1], bf[np * 2 + 1][0], bf[np * 2 + 1][1], bd);
            }
#pragma unroll
            for (int mi = 0; mi < 4; mi++)
#pragma unroll
                for (int ni = 0; ni < 4; ni++)
                    mma16(acc[mi][ni], af[mi], bf[ni]);
        }

        if (kt + 3 < KT) issue(kt + 3, (kt + 3) & (NSTG - 1));
        cp_commit();   // uniform group accounting
    }

    // epilogue
#pragma unroll
    for (int mi = 0; mi < 4; mi++) {
        int row0 = m0 + wm * 64 + mi * 16 + g;
#pragma unroll
        for (int ni = 0; ni < 4; ni++) {
            int col = n0 + wn * 32 + ni * 8 + 2 * c;
            float v0 = acc[mi][ni][0], v1 = acc[mi][ni][1];
            float v2 = acc[mi][ni][2], v3 = acc[mi][ni][3];
            if (MODE == 0) {
                v0 = v0 / (1.0f + __expf(-v0)); v1 = v1 / (1.0f + __expf(-v1));
                v2 = v2 / (1.0f + __expf(-v2)); v3 = v3 / (1.0f + __expf(-v3));
            }
            if (MODE == 2) { v0 *= escale; v1 *= escale; v2 *= escale; v3 *= escale; }
            if (OUT_HALF) {
                __half* Ch = (__half*)Cv;
                *(__half2*)(Ch + (size_t)row0 * N + col)       = __floats2half2_rn(v0, v1);
                *(__half2*)(Ch + (size_t)(row0 + 8) * N + col) = __floats2half2_rn(v2, v3);
            } else {
                float* Cf = (float*)Cv;
                float* p0 = Cf + (size_t)row0 * N + col;
                float* p1 = Cf + (size_t)(row0 + 8) * N + col;
                p0[0] = v0; p0[1] = v1;
                p1[0] = v2; p1[1] = v3;
            }
        }
    }
}

// ---------------------------------------------------------------------------
// Grouped adapter matvec + fused LayerNorm; writes (a_norm / 320) as fp16.
// ---------------------------------------------------------------------------
__global__ void __launch_bounds__(256)
adapter_grouped(const float* __restrict__ Wexp,
                const float* __restrict__ gamma,
                const float* __restrict__ beta) {
    __shared__ float a_sh[ADP][GRP];
    __shared__ float c_sh[GRP][ADP];
    __shared__ int s_tok[GRP];
    __shared__ int s_meta[3];

    const int b = blockIdx.x;
    if (threadIdx.x == 0) {
        int e = 0;
        while (e < NEXP && b >= g_blkoff[e + 1]) e++;
        if (e >= NEXP) s_meta[0] = -1;
        else {
            int base = g_off[e] + (b - g_blkoff[e]) * GRP;
            s_meta[0] = e; s_meta[1] = base;
            s_meta[2] = min(GRP, g_off[e + 1] - base);
        }
    }
    __syncthreads();
    const int e = s_meta[0];
    if (e < 0) return;
    const int base = s_meta[1], cnt = s_meta[2];

    if (threadIdx.x < GRP)
        s_tok[threadIdx.x] = (threadIdx.x < cnt) ? g_perm[base + threadIdx.x] : -1;
    __syncthreads();

    for (int i = threadIdx.x; i < ADP * GRP; i += 256) {
        int k = i >> 4, t = i & (GRP - 1);
        int tok = s_tok[t];
        a_sh[k][t] = (tok >= 0) ? g_A[tok * ADP + k] : 0.0f;
    }
    __syncthreads();

    const int o = threadIdx.x;
    float acc[GRP];
#pragma unroll
    for (int t = 0; t < GRP; t++) acc[t] = 0.0f;
    const float4* wr = (const float4*)(Wexp + ((size_t)e * ADP + o) * ADP);
#pragma unroll 4
    for (int k4 = 0; k4 < ADP / 4; k4++) {
        float4 w = wr[k4];
        float wv[4] = {w.x, w.y, w.z, w.w};
#pragma unroll
        for (int j = 0; j < 4; j++) {
            const float4* ap = (const float4*)&a_sh[k4 * 4 + j][0];
#pragma unroll
            for (int t4 = 0; t4 < GRP / 4; t4++) {
                float4 a = ap[t4];
                acc[t4 * 4 + 0] = fmaf(wv[j], a.x, acc[t4 * 4 + 0]);
                acc[t4 * 4 + 1] = fmaf(wv[j], a.y, acc[t4 * 4 + 1]);
                acc[t4 * 4 + 2] = fmaf(wv[j], a.z, acc[t4 * 4 + 2]);
                acc[t4 * 4 + 3] = fmaf(wv[j], a.w, acc[t4 * 4 + 3]);
            }
        }
    }
#pragma unroll
    for (int t = 0; t < GRP; t++) c_sh[t][o] = acc[t];
    __syncthreads();

    const int warp = threadIdx.x >> 5, lane = threadIdx.x & 31;
    for (int t = warp; t < GRP; t += 8) {
        if (t >= cnt) continue;
        float v[8], s = 0.0f;
#pragma unroll
        for (int j = 0; j < 8; j++) { v[j] = c_sh[t][lane + 32 * j]; s += v[j]; }
#pragma unroll
        for (int d = 16; d > 0; d >>= 1) s += __shfl_xor_sync(0xffffffffu, s, d);
        float mu = s * (1.0f / ADP), q = 0.0f;
#pragma unroll
        for (int j = 0; j < 8; j++) { float dd = v[j] - mu; q += dd * dd; }
#pragma unroll
        for (int d = 16; d > 0; d >>= 1) q += __shfl_xor_sync(0xffffffffu, q, d);
        float rs = rsqrtf(q * (1.0f / ADP) + 1e-5f);
        int tok = s_tok[t];
#pragma unroll
        for (int j = 0; j < 8; j++) {
            int oo = lane + 32 * j;
            float val = ((v[j] - mu) * rs * gamma[e * ADP + oo] + beta[e * ADP + oo])
                        * (1.0f / 320.0f);
            g_ANh[tok * ADP + oo] = __float2half(val);
        }
    }
}

// ---------------------------------------------------------------------------
// Launch
// ---------------------------------------------------------------------------
extern "C" void kernel_launch(void* const* d_in, const int* in_sizes, int n_in,
                              void* d_out, int out_size) {
    const float* x     = (const float*)d_in[0];
    const float* ew    = (const float*)d_in[1];
    const float* W_up  = (const float*)d_in[2];
    const float* W_ad  = (const float*)d_in[3];
    const float* W_exp = (const float*)d_in[4];
    const float* gamma = (const float*)d_in[5];
    const float* beta  = (const float*)d_in[6];
    const float* W_ep  = (const float*)d_in[7];
    const float* W_out = (const float*)d_in[8];
    float* out = (float*)d_out;

    void *pxh, *pWuph, *pWadh, *pWouth, *pWepTh, *pWch, *pHh, *pA, *pANh;
    cudaGetSymbolAddress(&pxh, g_xh);
    cudaGetSymbolAddress(&pWuph, g_Wuph);
    cudaGetSymbolAddress(&pWadh, g_Wadh);
    cudaGetSymbolAddress(&pWouth, g_Wouth);
    cudaGetSymbolAddress(&pWepTh, g_WepTh);
    cudaGetSymbolAddress(&pWch, g_Wch);
    cudaGetSymbolAddress(&pHh, g_Hh);
    cudaGetSymbolAddress(&pA, g_A);
    cudaGetSymbolAddress(&pANh, g_ANh);
    __half* xh     = (__half*)pxh;
    __half* Wuph   = (__half*)pWuph;
    __half* Wadh   = (__half*)pWadh;
    __half* Wouth  = (__half*)pWouth;
    __half* WepTh  = (__half*)pWepTh;
    __half* Wch    = (__half*)pWch;
    __half* Hh     = (__half*)pHh;
    float*  Aa     = (float*)pA;
    __half* ANh    = (__half*)pANh;

    cudaFuncSetAttribute(gemm_h<0, false, true>,  cudaFuncAttributeMaxDynamicSharedMemorySize, SMEM_TOTAL);
    cudaFuncSetAttribute(gemm_h<1, false, false>, cudaFuncAttributeMaxDynamicSharedMemorySize, SMEM_TOTAL);
    cudaFuncSetAttribute(gemm_h<1, false, true>,  cudaFuncAttributeMaxDynamicSharedMemorySize, SMEM_TOTAL);
    cudaFuncSetAttribute(gemm_h<2, true, false>,  cudaFuncAttributeMaxDynamicSharedMemorySize, SMEM_TOTAL);

    // 1-3: converts needed by the big GEMM
    cvt_kernel<<<T_TOK * D_EMB / 8 / 256, 256>>>(x, xh, T_TOK * D_EMB, 1.0f);
    cvt_kernel<<<HID * D_EMB / 8 / 256, 256>>>(W_up, Wuph, HID * D_EMB, 1.0f);
    init_kernel<<<1, 32>>>();

    // 4: H = silu(x @ W_up^T) -> fp16   (profiled launch)
    gemm_h<0, false, true><<<dim3(HID / 128, T_TOK / 128), 256, SMEM_TOTAL>>>(
        xh, Wuph, D_EMB, nullptr, nullptr, 0, Hh, T_TOK, HID, 1.0f);

    // 5-10: routing + remaining converts + Wc precompute
    route_kernel<<<(T_TOK + 255) / 256, 256>>>(ew);
    scan_kernel<<<1, 32>>>();
    cvt_kernel<<<ADP * HID / 8 / 256, 256>>>(W_ad, Wadh, ADP * HID, 1.0f);
    cvt_kernel<<<D_EMB * HID / 8 / 256, 256>>>(W_out, Wouth, D_EMB * HID, 32.0f);
    transpose_cvt_kernel<<<dim3(HID / 32, ADP / 32), dim3(32, 8)>>>(W_ep, WepTh);
    // Wc_h = (32 W_out) @ (32 W_ep) = 1024 * W_out@W_ep  -> fp16
    gemm_h<1, false, true><<<dim3(ADP / 128, D_EMB / 128), 256, SMEM_TOTAL>>>(
        Wouth, WepTh, HID, nullptr, nullptr, 0, Wch, D_EMB, ADP, 1.0f);

    // 11: scatter
    scatter_kernel<<<(T_TOK + 255) / 256, 256>>>();

    // 12: A = H @ W_adapt^T  (fp32 out for adapter)
    gemm_h<1, false, false><<<dim3(ADP / 128, T_TOK / 128), 256, SMEM_TOTAL>>>(
        Hh, Wadh, HID, nullptr, nullptr, 0, Aa, T_TOK, ADP, 1.0f);

    // 13: adapter + LN -> ANh (= a_norm/320)
    adapter_grouped<<<T_TOK / GRP + NEXP, 256>>>(W_exp, gamma, beta);

    // 14: out = (1/32) * [H | ANh] @ [32W_out | 1024Wc]^T
    //     shared: 32/32 = 1 ; expert: 1024/(320*32) = 0.1  (exact)
    gemm_h<2, true, false><<<dim3(D_EMB / 128, T_TOK / 128), 256, SMEM_TOTAL>>>(
        Hh, Wouth, HID, ANh, Wch, ADP, out, T_TOK, D_EMB, 1.0f / 32.0f);
}